// round 14
// baseline (speedup 1.0000x reference)
#include <cuda_runtime.h>
#include <cuda_fp16.h>
#include <math.h>

#define NB 2
#define DD 16
#define HH 32
#define WW 32
#define CC 64
#define GG 4
#define GCH 16
#define PP 27
#define DINP 18
#define HINP 34
#define WINP 34
#define PVX 8         // voxels per block (proj kernel)
#define VX 16         // voxels per block (fused kernel)

typedef unsigned long long u64;

// ---- packed f32x2 helpers (sm_103a dual-FMA) ----
__device__ __forceinline__ u64 pk2(float lo, float hi) {
    u64 r; asm("mov.b64 %0, {%1, %2};" : "=l"(r) : "f"(lo), "f"(hi)); return r;
}
__device__ __forceinline__ float2 upk2(u64 v) {
    float2 r; asm("mov.b64 {%0, %1}, %2;" : "=f"(r.x), "=f"(r.y) : "l"(v)); return r;
}
__device__ __forceinline__ void fma2(u64& acc, u64 a, u64 b) {
    asm("fma.rn.f32x2 %0, %1, %2, %0;" : "+l"(acc) : "l"(a), "l"(b));
}

// padded value buffer, fp16, group-major: [n][g][z][y][x][16ch], ~5.3 MB.
// Border cells are NEVER written; they rely on static zero-initialization.
__device__ __half g_xph[(size_t)NB * GG * DINP * HINP * WINP * GCH];
// heads weights pre-packed as fp16 mma B-fragments (54 n-tiles x 4 k-steps)
__device__ uint2 g_wB[54 * 4 * 32];
// out_w pre-packed the same way: 8 n-tiles
__device__ uint2 g_wO[8 * 4 * 32];

// fused-kernel dynamic smem layout (bytes):
#define SM_SLAB   0                         // 3*3*18*64 f32 = 41472
#define SM_DWW    41472                     // 1728 f32 = 6912
#define SM_PA     0                         // params overlay slab: 1728 float2
#define SM_PB     13824
#define SM_PC     27648                     // 1728 int2 -> ends 41472
#define SM_OFFS   48384                     // 16*324 f32 = 20736
#define SM_OUTH   48384                     // 4 quarters * 16*64 half = 8192 (overlay)
#define SM_MASKV  69120                     // 16*108 f32 = 6912
#define SM_X1S    76032                     // 16*64 f32 = 4096 (res overlays)
#define SM_X1H    80128                     // 16*64 half = 2048
#define SM_TOTAL  82176

// ---------------------------------------------------------------------------
// Multi-voxel half-warp reduction (proj kernel): 15 shuffles for 8 dots.
// ---------------------------------------------------------------------------
__device__ __forceinline__ float multi_reduce8(float p[PVX], int hl)
{
#pragma unroll
    for (int v = 0; v < 8; v++) p[v] += __shfl_xor_sync(0xffffffffu, p[v], 8);
    float q[4];
    bool b4 = (hl & 4) != 0;
#pragma unroll
    for (int j = 0; j < 4; j++) {
        float send = b4 ? p[j] : p[j + 4];
        float recv = __shfl_xor_sync(0xffffffffu, send, 4);
        q[j] = (b4 ? p[j + 4] : p[j]) + recv;
    }
    float s[2];
    bool b2 = (hl & 2) != 0;
#pragma unroll
    for (int j = 0; j < 2; j++) {
        float send = b2 ? q[j] : q[j + 2];
        float recv = __shfl_xor_sync(0xffffffffu, send, 2);
        s[j] = (b2 ? q[j + 2] : q[j]) + recv;
    }
    bool b1 = (hl & 1) != 0;
    float send = b1 ? s[0] : s[1];
    float recv = __shfl_xor_sync(0xffffffffu, send, 1);
    return (b1 ? s[1] : s[0]) + recv;
}

// ---------------------------------------------------------------------------
// Kernel 1: value projection -> fp16 group-major padded buffer (interior
// voxels only). Blocks 0..31 also pack g_wB/g_wO (consumed only by kernel 2).
// ---------------------------------------------------------------------------
__global__ void __launch_bounds__(256, 4) proj_pad_kernel(
    const float* __restrict__ input,
    const float* __restrict__ in_w,
    const float* __restrict__ in_b,
    const float* __restrict__ off_w,
    const float* __restrict__ mask_w,
    const float* __restrict__ out_w)
{
    int tid = threadIdx.x;
    int vb = blockIdx.x * PVX;             // OUTPUT voxel index (interior)
    int x0 = vb % WW; int t = vb / WW;
    int y = t % HH; t /= HH;
    int z = t % DD; int n = t / DD;

    // side duty: pack head + out_w weights into mma B-fragment layout (fp16)
    if (blockIdx.x < 32) {
        int i = blockIdx.x * 256 + tid;    // 0..8191
        if (i < 54 * 4 * 32) {
            int nt = i >> 7;
            int rem = i & 127;
            int ks = rem >> 5, ln = rem & 31;
            int g = ln >> 2, tg = ln & 3;
            int nrow = nt * 8 + g;
            int k0 = ks * 16 + tg * 2;
            const float* wr = (nrow < 324) ? off_w + (size_t)nrow * CC
                                           : mask_w + (size_t)(nrow - 324) * CC;
            __half2 lo = __floats2half2_rn(wr[k0], wr[k0 + 1]);
            __half2 hi = __floats2half2_rn(wr[k0 + 8], wr[k0 + 9]);
            uint2 u;
            ((__half2*)&u)[0] = lo;
            ((__half2*)&u)[1] = hi;
            g_wB[i] = u;
        } else if (i < 54 * 4 * 32 + 8 * 4 * 32) {
            int j = i - 54 * 4 * 32;
            int nt = j >> 7;
            int rem = j & 127;
            int ks = rem >> 5, ln = rem & 31;
            int g = ln >> 2, tg = ln & 3;
            int nrow = nt * 8 + g;
            int k0 = ks * 16 + tg * 2;
            const float* wr = out_w + (size_t)nrow * CC;
            __half2 lo = __floats2half2_rn(wr[k0], wr[k0 + 1]);
            __half2 hi = __floats2half2_rn(wr[k0 + 8], wr[k0 + 9]);
            uint2 u;
            ((__half2*)&u)[0] = lo;
            ((__half2*)&u)[1] = hi;
            g_wO[j] = u;
        }
    }

    __shared__ __align__(16) float shx[PVX * CC];
    __shared__ __align__(16) float res[PVX * CC];

    // stage 8 input voxels (always in-bounds)
    {
        const float* ip = input + ((size_t)((n * DD + z) * HH + y) * WW + x0) * CC;
        for (int o = tid; o < PVX * CC / 4; o += 256)
            ((float4*)shx)[o] = ((const float4*)ip)[o];
    }
    __syncthreads();

    // GEMV: 2 rows per warp, float4 per half-warp lane, direct in_w (coalesced)
    {
        int lane = tid & 31, warp = tid >> 5;
        int half = lane >> 4, hl = lane & 15;
        float4 xv[PVX];
#pragma unroll
        for (int v = 0; v < PVX; v++) xv[v] = ((const float4*)shx)[v * 16 + hl];
#pragma unroll
        for (int i = 0; i < 4; i++) {
            int r = i * 16 + warp * 2 + half;
            float4 w = ((const float4*)(in_w + (size_t)r * CC))[hl];
            u64 wa = pk2(w.x, w.y), wb = pk2(w.z, w.w);
            float p[PVX];
#pragma unroll
            for (int v = 0; v < PVX; v++) {
                u64 acc = 0ull;
                fma2(acc, wa, pk2(xv[v].x, xv[v].y));
                fma2(acc, wb, pk2(xv[v].z, xv[v].w));
                float2 tv = upk2(acc);
                p[v] = tv.x + tv.y;
            }
            float tot = multi_reduce8(p, hl);
            if (hl < 8)
                res[hl * CC + r] = tot + in_b[r];
        }
    }
    __syncthreads();

    // write fp16 group-major at padded coords (z+1, y+1, x0+v+1)
    if (tid < PVX * CC / 4) {              // 128 chunks
        int o = tid;
        int v = o >> 4, g = (o >> 2) & 3, c4 = o & 3;
        const float* s = res + v * CC + g * GCH + c4 * 4;
        __half2 h01 = __floats2half2_rn(s[0], s[1]);
        __half2 h23 = __floats2half2_rn(s[2], s[3]);
        uint2 u;
        ((__half2*)&u)[0] = h01;
        ((__half2*)&u)[1] = h23;
        size_t base = ((size_t)(((n * GG + g) * DINP + (z + 1)) * HINP + (y + 1)) * WINP
                       + (x0 + v + 1)) * GCH;
        *(uint2*)(g_xph + base + c4 * 4) = u;
    }
}

// ---------------------------------------------------------------------------
// Kernel 2: fused pipeline, 16 consecutive x-voxels per block, 512 threads,
// 2 blocks/SM, dynamic smem (82176 B) with overlays per the SM_* map.
// ---------------------------------------------------------------------------
__global__ void __launch_bounds__(512, 2) dcnv3_fused_kernel(
    const float* __restrict__ input,
    const float* __restrict__ dw_w,
    const float* __restrict__ dw_b,
    const float* __restrict__ ln_g,
    const float* __restrict__ ln_b,
    const float* __restrict__ off_b,
    const float* __restrict__ mask_b,
    const float* __restrict__ out_b,
    float* __restrict__ out)
{
    extern __shared__ __align__(16) char smem_raw[];
    float*  slab  = (float*)(smem_raw + SM_SLAB);   // 3*3*18*64
    float*  dwws  = (float*)(smem_raw + SM_DWW);    // 64*27
    float2* pA    = (float2*)(smem_raw + SM_PA);    // [m*(1-fz), m*fz]
    float2* pB    = (float2*)(smem_raw + SM_PB);    // [fx, fy]
    int2*   pC    = (int2*)(smem_raw + SM_PC);      // [base, boundbits]
    float*  offs  = (float*)(smem_raw + SM_OFFS);   // 16*324
    __half* outh  = (__half*)(smem_raw + SM_OUTH);  // 4 * 16*64 (overlays offs)
    float*  maskv = (float*)(smem_raw + SM_MASKV);  // 16*108
    float*  x1s   = (float*)(smem_raw + SM_X1S);    // 16*64
    float*  res   = (float*)(smem_raw + SM_X1S);    // overlays x1s
    __half* x1h   = (__half*)(smem_raw + SM_X1H);   // 16*64

    int tid = threadIdx.x;
    int vb = blockIdx.x * VX;
    int x0 = vb % WW; int t = vb / WW;
    int y = t % HH; t /= HH;
    int z = t % DD; int n = t / DD;

    int lane = tid & 31, warp = tid >> 5;

    // ---- phase 1a: stage dw weights + input slab (3 x 3 x 18 x 64) ----
    for (int e = tid; e < CC * 27 / 4; e += 512)            // 432 float4
        ((float4*)dwws)[e] = ((const float4*)dw_w)[e];
    bool zy_int = (z >= 1) && (z <= DD - 2) && (y >= 1) && (y <= HH - 2);
    if (zy_int) {
        const float* ib = input + ((size_t)((n * DD + z - 1) * HH + y - 1) * WW) * CC;
        for (int e = tid; e < 3 * 3 * 18 * 16; e += 512) {  // 2592 float4
            int c4 = e & 15;
            int xx = (e >> 4) % 18;
            int r = e / 288;
            int yy = r % 3, zz = r / 3;
            int gx = x0 + xx - 1;
            float4 val = make_float4(0.f, 0.f, 0.f, 0.f);
            if ((unsigned)gx < WW)
                val = ((const float4*)(ib + ((size_t)(zz * HH + yy) * WW + gx) * CC))[c4];
            ((float4*)slab)[e] = val;
        }
    } else {
        for (int e = tid; e < 3 * 3 * 18 * 16; e += 512) {
            int c4 = e & 15;
            int xx = (e >> 4) % 18;
            int r = e / 288;
            int yy = r % 3, zz = r / 3;
            int gz = z + zz - 1, gy = y + yy - 1, gx = x0 + xx - 1;
            float4 val = make_float4(0.f, 0.f, 0.f, 0.f);
            if ((unsigned)gz < DD && (unsigned)gy < HH && (unsigned)gx < WW)
                val = ((const float4*)(input + ((size_t)((n * DD + gz) * HH + gy) * WW + gx) * CC))[c4];
            ((float4*)slab)[e] = val;
        }
    }
    __syncthreads();

    // ---- phase 1b: depthwise conv, sliding window in x (18-wide slab) ----
    {
        int c = tid & 63, pair = tid >> 6;     // pair in 0..7
        int v0 = pair * 2;
        float acc0 = dw_b[c], acc1 = acc0;
#pragma unroll
        for (int zz = 0; zz < 3; zz++) {
#pragma unroll
            for (int yy = 0; yy < 3; yy++) {
                const float* srow = slab + ((zz * 3 + yy) * 18 + v0) * CC + c;
                const float* wrow = dwws + c * 27 + zz * 9 + yy * 3;
                float s0 = srow[0];
                float s1 = srow[CC];
                float s2 = srow[2 * CC];
                float s3 = srow[3 * CC];
                float w0 = wrow[0], w1 = wrow[1], w2 = wrow[2];
                acc0 = fmaf(s0, w0, fmaf(s1, w1, fmaf(s2, w2, acc0)));
                acc1 = fmaf(s1, w0, fmaf(s2, w1, fmaf(s3, w2, acc1)));
            }
        }
        x1s[v0 * CC + c] = acc0;
        x1s[(v0 + 1) * CC + c] = acc1;
    }
    __syncthreads();

    // ---- phase 2: LayerNorm + exact GELU (warp = voxel, 16 warps) ----
    {
        int v = warp;
        float a = x1s[v * CC + lane];
        float b = x1s[v * CC + lane + 32];
        float s = a + b, s2 = a * a + b * b;
#pragma unroll
        for (int o = 16; o > 0; o >>= 1) {
            s  += __shfl_xor_sync(0xffffffffu, s,  o);
            s2 += __shfl_xor_sync(0xffffffffu, s2, o);
        }
        float mean = s * (1.0f / CC);
        float var  = s2 * (1.0f / CC) - mean * mean;
        float rstd = rsqrtf(var + 1e-6f);
        a = (a - mean) * rstd * ln_g[lane] + ln_b[lane];
        b = (b - mean) * rstd * ln_g[lane + 32] + ln_b[lane + 32];
        a = 0.5f * a * (1.0f + erff(a * 0.70710678118654752f));
        b = 0.5f * b * (1.0f + erff(b * 0.70710678118654752f));
        x1h[v * CC + lane]      = __float2half(a);
        x1h[v * CC + lane + 32] = __float2half(b);
    }
    __syncthreads();

    // ---- phase 3: heads GEMM on tensor cores, FULL 16-row A (16 voxels) ----
    {
        int g = lane >> 2, tg = lane & 3;
        unsigned a0[4], a1[4], a2[4], a3[4];
        const __half* xr = x1h + g * CC;
#pragma unroll
        for (int ks = 0; ks < 4; ks++) {
            a0[ks] = *(const unsigned*)(xr + ks * 16 + tg * 2);
            a1[ks] = *(const unsigned*)(xr + 8 * CC + ks * 16 + tg * 2);
            a2[ks] = *(const unsigned*)(xr + ks * 16 + 8 + tg * 2);
            a3[ks] = *(const unsigned*)(xr + 8 * CC + ks * 16 + 8 + tg * 2);
        }
        for (int nt = warp; nt < 54; nt += 16) {
            float c0 = 0.f, c1 = 0.f, c2 = 0.f, c3 = 0.f;
#pragma unroll
            for (int ks = 0; ks < 4; ks++) {
                uint2 wq = g_wB[(nt * 4 + ks) * 32 + lane];
                asm volatile(
                    "mma.sync.aligned.m16n8k16.row.col.f32.f16.f16.f32 "
                    "{%0,%1,%2,%3},{%4,%5,%6,%7},{%8,%9},{%0,%1,%2,%3};"
                    : "+f"(c0), "+f"(c1), "+f"(c2), "+f"(c3)
                    : "r"(a0[ks]), "r"(a1[ks]), "r"(a2[ks]), "r"(a3[ks]),
                      "r"(wq.x), "r"(wq.y));
            }
            int n0 = nt * 8 + tg * 2;              // even; n0,n0+1 same head
            if (n0 < 324) {
                float2 bb = *(const float2*)(off_b + n0);
                *(float2*)(offs + g * 324 + n0) =
                    make_float2(c0 + bb.x, c1 + bb.y);
                *(float2*)(offs + (g + 8) * 324 + n0) =
                    make_float2(c2 + bb.x, c3 + bb.y);
            } else {
                float2 bb = *(const float2*)(mask_b + (n0 - 324));
                *(float2*)(maskv + g * 108 + (n0 - 324)) =
                    make_float2(c0 + bb.x, c1 + bb.y);
                *(float2*)(maskv + (g + 8) * 108 + (n0 - 324)) =
                    make_float2(c2 + bb.x, c3 + bb.y);
            }
        }
    }
    __syncthreads();

    // ---- phase 4: softmax over P per (voxel, group): 64 rows / 16 warps ----
    {
#pragma unroll
        for (int rr = 0; rr < 4; rr++) {
            int row = warp * 4 + rr;
            float val = (lane < PP) ? maskv[row * PP + lane] : -1e30f;
            float mx = val;
#pragma unroll
            for (int o = 16; o > 0; o >>= 1)
                mx = fmaxf(mx, __shfl_xor_sync(0xffffffffu, mx, o));
            float e = (lane < PP) ? __expf(val - mx) : 0.0f;
            float s = e;
#pragma unroll
            for (int o = 16; o > 0; o >>= 1)
                s += __shfl_xor_sync(0xffffffffu, s, o);
            if (lane < PP) maskv[row * PP + lane] = __fdividef(e, s);
        }
    }
    __syncthreads();

    // ---- phase 4.5: packed sampling params, e = (g*27+p)*16 + v ----
    for (int e = tid; e < VX * GG * PP; e += 512) {
        int v = e & 15, gp = e >> 4;
        int g = gp / 27, p = gp % 27;
        int i0 = p / 9, i1 = (p / 3) % 3, i2 = p % 3;       // (kw, kh, kd)
        const float* ofv = offs + v * 324 + (g * 27 + p) * 3;
        float px = (float)(x0 + v + i0) + ofv[0];
        float py = (float)(y + i1) + ofv[1];
        float pz = (float)(z + i2) + ofv[2];
        float fx0 = floorf(px), fy0 = floorf(py), fz0 = floorf(pz);
        int xi = (int)fx0, yi = (int)fy0, zi = (int)fz0;
        float fz = pz - fz0;
        float m  = maskv[v * 108 + g * 27 + p];
        pA[e] = make_float2(m * (1.0f - fz), m * fz);
        pB[e] = make_float2(px - fx0, py - fy0);
        int mbits = ((unsigned)xi       < WINP ?  1 : 0)
                  | ((unsigned)(xi + 1) < WINP ?  2 : 0)
                  | ((unsigned)yi       < HINP ?  4 : 0)
                  | ((unsigned)(yi + 1) < HINP ?  8 : 0)
                  | ((unsigned)zi       < DINP ? 16 : 0)
                  | ((unsigned)(zi + 1) < DINP ? 32 : 0);
        int base = ((zi * HINP + yi) * WINP + xi) * GCH;
        pC[e] = make_int2(base, mbits);
    }
    __syncthreads();

    // ---- phase 5: deformable trilinear sampling ----
    // warp = (g, point-quarter pq); lane = (v16, q2). One warp-LDG per corner
    // covers all 16 voxels' 16B q2-halves -> 512B contiguous span.
    {
        int q2 = lane & 1, v = lane >> 1;
        int g = warp >> 2, pq = warp & 3;
        int pstart = pq * 7;
        int pend   = (pq == 3) ? 27 : pstart + 7;
        __half* outp = outh + pq * (VX * CC);
        const __half* xgl = g_xph +
            (size_t)(n * GG + g) * (DINP * HINP * WINP) * GCH + q2 * 8;
        float4 aA = make_float4(0.f, 0.f, 0.f, 0.f);
        float4 aB = make_float4(0.f, 0.f, 0.f, 0.f);
        for (int p = pstart; p < pend; p++) {
            int idx = (g * 27 + p) * 16 + v;
            float2 wzp = pA[idx];                  // mask pre-folded z weights
            float2 fxy = pB[idx];
            int2   bm  = pC[idx];
            int mb = bm.y;
            float wx0 = 1.0f - fxy.x, wx1 = fxy.x;
            float wy0 = 1.0f - fxy.y, wy1 = fxy.y;
            const __half* bp = xgl + bm.x;
#pragma unroll
            for (int dz = 0; dz < 2; dz++) {
                bool bz = (mb & (16 << dz)) != 0;
                float wz = dz ? wzp.y : wzp.x;
#pragma unroll
                for (int dy = 0; dy < 2; dy++) {
                    float wzy = wz * (dy ? wy1 : wy0);
                    bool bzy = bz && ((mb & (4 << dy)) != 0);
#pragma unroll
                    for (int dx = 0; dx < 2; dx++) {
                        if (bzy && ((mb >> dx) & 1)) {
                            float wt = wzy * (dx ? wx1 : wx0);
                            uint4 raw = *(const uint4*)(bp +
                                ((dz * HINP + dy) * WINP + dx) * GCH);
                            const __half2* hp = (const __half2*)&raw;
                            float2 f0 = __half22float2(hp[0]);
                            float2 f1 = __half22float2(hp[1]);
                            float2 f2 = __half22float2(hp[2]);
                            float2 f3 = __half22float2(hp[3]);
                            aA.x = fmaf(wt, f0.x, aA.x);
                            aA.y = fmaf(wt, f0.y, aA.y);
                            aA.z = fmaf(wt, f1.x, aA.z);
                            aA.w = fmaf(wt, f1.y, aA.w);
                            aB.x = fmaf(wt, f2.x, aB.x);
                            aB.y = fmaf(wt, f2.y, aB.y);
                            aB.z = fmaf(wt, f3.x, aB.z);
                            aB.w = fmaf(wt, f3.y, aB.w);
                        }
                    }
                }
            }
        }
        // every lane owns distinct (v, q2) -> direct fp16 store, no reduce
        uint4 u;
        ((__half2*)&u)[0] = __floats2half2_rn(aA.x, aA.y);
        ((__half2*)&u)[1] = __floats2half2_rn(aA.z, aA.w);
        ((__half2*)&u)[2] = __floats2half2_rn(aB.x, aB.y);
        ((__half2*)&u)[3] = __floats2half2_rn(aB.z, aB.w);
        *(uint4*)(outp + v * CC + g * GCH + q2 * 8) = u;
    }
    __syncthreads();

    // ---- phase 6: output projection on tensor cores, full 16-row A ----
    if (warp < 8) {
        int g = lane >> 2, tg = lane & 3;
        const __half* x0p = outh + g * CC;
        const __half* x1p = outh + (VX * CC) + g * CC;
        const __half* x2p = outh + 2 * (VX * CC) + g * CC;
        const __half* x3p = outh + 3 * (VX * CC) + g * CC;
        unsigned a0[4], a1[4], a2[4], a3[4];
#pragma unroll
        for (int ks = 0; ks < 4; ks++) {
#pragma unroll
            for (int part = 0; part < 4; part++) {
                int off = ks * 16 + tg * 2 + ((part & 1) ? 8 : 0)
                        + ((part & 2) ? 8 * CC : 0);
                __half2 sA = __hadd2(*(const __half2*)(x0p + off),
                                     *(const __half2*)(x1p + off));
                __half2 sB = __hadd2(*(const __half2*)(x2p + off),
                                     *(const __half2*)(x3p + off));
                __half2 sT = __hadd2(sA, sB);
                unsigned uv = *(unsigned*)&sT;
                if (part == 0) a0[ks] = uv;
                else if (part == 1) a2[ks] = uv;
                else if (part == 2) a1[ks] = uv;
                else a3[ks] = uv;
            }
        }
        int nt = warp;                             // 8 warps, 8 n-tiles
        float c0 = 0.f, c1 = 0.f, c2 = 0.f, c3 = 0.f;
#pragma unroll
        for (int ks = 0; ks < 4; ks++) {
            uint2 wq = g_wO[(nt * 4 + ks) * 32 + lane];
            asm volatile(
                "mma.sync.aligned.m16n8k16.row.col.f32.f16.f16.f32 "
                "{%0,%1,%2,%3},{%4,%5,%6,%7},{%8,%9},{%0,%1,%2,%3};"
                : "+f"(c0), "+f"(c1), "+f"(c2), "+f"(c3)
                : "r"(a0[ks]), "r"(a1[ks]), "r"(a2[ks]), "r"(a3[ks]),
                  "r"(wq.x), "r"(wq.y));
        }
        int n0 = nt * 8 + tg * 2;
        float2 bb = *(const float2*)(out_b + n0);
        *(float2*)(res + g * CC + n0) = make_float2(c0 + bb.x, c1 + bb.y);
        *(float2*)(res + (g + 8) * CC + n0) = make_float2(c2 + bb.x, c3 + bb.y);
    }
    __syncthreads();

    if (tid < VX * CC / 4)
        ((float4*)(out + (size_t)vb * CC))[tid] = ((const float4*)res)[tid];
}

extern "C" void kernel_launch(void* const* d_in, const int* in_sizes, int n_in,
                              void* d_out, int out_size)
{
    const float* input  = (const float*)d_in[0];
    const float* dw_w   = (const float*)d_in[1];
    const float* dw_b   = (const float*)d_in[2];
    const float* ln_g   = (const float*)d_in[3];
    const float* ln_b   = (const float*)d_in[4];
    const float* off_w  = (const float*)d_in[5];
    const float* off_b  = (const float*)d_in[6];
    const float* mask_w = (const float*)d_in[7];
    const float* mask_b = (const float*)d_in[8];
    const float* in_w   = (const float*)d_in[9];
    const float* in_b   = (const float*)d_in[10];
    const float* out_w  = (const float*)d_in[11];
    const float* out_b  = (const float*)d_in[12];
    float* out = (float*)d_out;

    cudaFuncSetAttribute(dcnv3_fused_kernel,
                         cudaFuncAttributeMaxDynamicSharedMemorySize, SM_TOTAL);

    int proj_blocks  = NB * DD * HH * WW / PVX;        // 4096
    int fused_blocks = NB * DD * HH * WW / VX;         // 2048

    proj_pad_kernel<<<proj_blocks, 256>>>(input, in_w, in_b, off_w, mask_w, out_w);
    dcnv3_fused_kernel<<<fused_blocks, 512, SM_TOTAL>>>(
        input, dw_w, dw_b, ln_g, ln_b,
        off_b, mask_b, out_b, out);
}

// round 15
// speedup vs baseline: 1.1427x; 1.1427x over previous
#include <cuda_runtime.h>
#include <cuda_fp16.h>
#include <math.h>

#define NB 2
#define DD 16
#define HH 32
#define WW 32
#define CC 64
#define GG 4
#define GCH 16
#define PP 27
#define DINP 18
#define HINP 34
#define WINP 34
#define VX 8          // voxels per block

typedef unsigned long long u64;

// ---- packed f32x2 helpers (sm_103a dual-FMA) ----
__device__ __forceinline__ u64 pk2(float lo, float hi) {
    u64 r; asm("mov.b64 %0, {%1, %2};" : "=l"(r) : "f"(lo), "f"(hi)); return r;
}
__device__ __forceinline__ float2 upk2(u64 v) {
    float2 r; asm("mov.b64 {%0, %1}, %2;" : "=f"(r.x), "=f"(r.y) : "l"(v)); return r;
}
__device__ __forceinline__ void fma2(u64& acc, u64 a, u64 b) {
    asm("fma.rn.f32x2 %0, %1, %2, %0;" : "+l"(acc) : "l"(a), "l"(b));
}

// padded value buffer, fp16, group-major: [n][g][z][y][x][16ch], ~5.3 MB.
// Border cells are NEVER written; they rely on static zero-initialization.
__device__ __half g_xph[(size_t)NB * GG * DINP * HINP * WINP * GCH];
// heads weights pre-packed as fp16 mma B-fragments (54 n-tiles x 4 k-steps)
__device__ uint2 g_wB[54 * 4 * 32];
// out_w pre-packed the same way: 8 n-tiles
__device__ uint2 g_wO[8 * 4 * 32];

// ---------------------------------------------------------------------------
// Multi-voxel half-warp reduction (proj kernel): 15 shuffles for 8 dots.
// ---------------------------------------------------------------------------
__device__ __forceinline__ float multi_reduce8(float p[VX], int hl)
{
#pragma unroll
    for (int v = 0; v < 8; v++) p[v] += __shfl_xor_sync(0xffffffffu, p[v], 8);
    float q[4];
    bool b4 = (hl & 4) != 0;
#pragma unroll
    for (int j = 0; j < 4; j++) {
        float send = b4 ? p[j] : p[j + 4];
        float recv = __shfl_xor_sync(0xffffffffu, send, 4);
        q[j] = (b4 ? p[j + 4] : p[j]) + recv;
    }
    float s[2];
    bool b2 = (hl & 2) != 0;
#pragma unroll
    for (int j = 0; j < 2; j++) {
        float send = b2 ? q[j] : q[j + 2];
        float recv = __shfl_xor_sync(0xffffffffu, send, 2);
        s[j] = (b2 ? q[j + 2] : q[j]) + recv;
    }
    bool b1 = (hl & 1) != 0;
    float send = b1 ? s[0] : s[1];
    float recv = __shfl_xor_sync(0xffffffffu, send, 1);
    return (b1 ? s[1] : s[0]) + recv;
}

// ---------------------------------------------------------------------------
// Kernel 1: value projection -> fp16 group-major padded buffer (interior
// voxels only). Blocks 0..31 also pack g_wB/g_wO (consumed only by kernel 2).
// ---------------------------------------------------------------------------
__global__ void __launch_bounds__(256, 4) proj_pad_kernel(
    const float* __restrict__ input,
    const float* __restrict__ in_w,
    const float* __restrict__ in_b,
    const float* __restrict__ off_w,
    const float* __restrict__ mask_w,
    const float* __restrict__ out_w)
{
    int tid = threadIdx.x;
    int vb = blockIdx.x * VX;              // OUTPUT voxel index (interior)
    int x0 = vb % WW; int t = vb / WW;
    int y = t % HH; t /= HH;
    int z = t % DD; int n = t / DD;

    // side duty: pack head + out_w weights into mma B-fragment layout (fp16)
    if (blockIdx.x < 32) {
        int i = blockIdx.x * 256 + tid;    // 0..8191
        if (i < 54 * 4 * 32) {
            int nt = i >> 7;
            int rem = i & 127;
            int ks = rem >> 5, ln = rem & 31;
            int g = ln >> 2, tg = ln & 3;
            int nrow = nt * 8 + g;
            int k0 = ks * 16 + tg * 2;
            const float* wr = (nrow < 324) ? off_w + (size_t)nrow * CC
                                           : mask_w + (size_t)(nrow - 324) * CC;
            __half2 lo = __floats2half2_rn(wr[k0], wr[k0 + 1]);
            __half2 hi = __floats2half2_rn(wr[k0 + 8], wr[k0 + 9]);
            uint2 u;
            ((__half2*)&u)[0] = lo;
            ((__half2*)&u)[1] = hi;
            g_wB[i] = u;
        } else if (i < 54 * 4 * 32 + 8 * 4 * 32) {
            int j = i - 54 * 4 * 32;
            int nt = j >> 7;
            int rem = j & 127;
            int ks = rem >> 5, ln = rem & 31;
            int g = ln >> 2, tg = ln & 3;
            int nrow = nt * 8 + g;
            int k0 = ks * 16 + tg * 2;
            const float* wr = out_w + (size_t)nrow * CC;
            __half2 lo = __floats2half2_rn(wr[k0], wr[k0 + 1]);
            __half2 hi = __floats2half2_rn(wr[k0 + 8], wr[k0 + 9]);
            uint2 u;
            ((__half2*)&u)[0] = lo;
            ((__half2*)&u)[1] = hi;
            g_wO[j] = u;
        }
    }

    __shared__ __align__(16) float shx[VX * CC];
    __shared__ __align__(16) float res[VX * CC];

    // stage 8 input voxels (always in-bounds)
    {
        const float* ip = input + ((size_t)((n * DD + z) * HH + y) * WW + x0) * CC;
        for (int o = tid; o < VX * CC / 4; o += 256)
            ((float4*)shx)[o] = ((const float4*)ip)[o];
    }
    __syncthreads();

    // GEMV: 2 rows per warp, float4 per half-warp lane, direct in_w (coalesced)
    {
        int lane = tid & 31, warp = tid >> 5;
        int half = lane >> 4, hl = lane & 15;
        float4 xv[VX];
#pragma unroll
        for (int v = 0; v < VX; v++) xv[v] = ((const float4*)shx)[v * 16 + hl];
#pragma unroll
        for (int i = 0; i < 4; i++) {
            int r = i * 16 + warp * 2 + half;
            float4 w = ((const float4*)(in_w + (size_t)r * CC))[hl];
            u64 wa = pk2(w.x, w.y), wb = pk2(w.z, w.w);
            float p[VX];
#pragma unroll
            for (int v = 0; v < VX; v++) {
                u64 acc = 0ull;
                fma2(acc, wa, pk2(xv[v].x, xv[v].y));
                fma2(acc, wb, pk2(xv[v].z, xv[v].w));
                float2 tv = upk2(acc);
                p[v] = tv.x + tv.y;
            }
            float tot = multi_reduce8(p, hl);
            if (hl < 8)
                res[hl * CC + r] = tot + in_b[r];
        }
    }
    __syncthreads();

    // write fp16 group-major at padded coords (z+1, y+1, x0+v+1)
    if (tid < VX * CC / 4) {               // 128 chunks
        int o = tid;
        int v = o >> 4, g = (o >> 2) & 3, c4 = o & 3;
        const float* s = res + v * CC + g * GCH + c4 * 4;
        __half2 h01 = __floats2half2_rn(s[0], s[1]);
        __half2 h23 = __floats2half2_rn(s[2], s[3]);
        uint2 u;
        ((__half2*)&u)[0] = h01;
        ((__half2*)&u)[1] = h23;
        size_t base = ((size_t)(((n * GG + g) * DINP + (z + 1)) * HINP + (y + 1)) * WINP
                       + (x0 + v + 1)) * GCH;
        *(uint2*)(g_xph + base + c4 * 4) = u;
    }
}

// ---------------------------------------------------------------------------
// Kernel 2: fused pipeline, 8 consecutive x-voxels per block, 256 threads,
// 5 blocks/SM (51-reg cap, 44800B smem). Overlays:
//   [0, 29952)      : phase 1 = slab(23040)+dwws(6912); phase >=4.5 = params
//                     (pA 0..6912, pB 6912..13824, pC 13824..20736)
//   [29952, 40320)  : offs (phase 3-4.5); outhA/outhB fp16 (phase 5-6)
//   [40320, 43776)  : maskv (ph 3-4.5); x1s (ph 1b-2); res (ph 6)
//   [43776, 44800)  : x1h fp16 (phase 2-3)
// ---------------------------------------------------------------------------
__global__ void __launch_bounds__(256, 5) dcnv3_fused_kernel(
    const float* __restrict__ input,
    const float* __restrict__ dw_w,
    const float* __restrict__ dw_b,
    const float* __restrict__ ln_g,
    const float* __restrict__ ln_b,
    const float* __restrict__ off_b,
    const float* __restrict__ mask_b,
    const float* __restrict__ out_b,
    float* __restrict__ out)
{
    __shared__ __align__(16) char smem_raw[44800];
    float*  slab  = (float*)smem_raw;               // 5760 floats
    float*  dwws  = slab + 5760;                    // 1728 floats
    float2* pA    = (float2*)smem_raw;              // [m*(1-fz), m*fz]
    float2* pB    = pA + 864;                       // [fx, fy]
    int2*   pC    = (int2*)(pB + 864);              // [base, boundbits]
    float*  offs  = (float*)(smem_raw + 29952);     // 2592 floats
    __half* outhA = (__half*)offs;                  // 512 halves (overlay)
    __half* outhB = outhA + 512;                    // 512 halves
    float*  maskv = (float*)(smem_raw + 40320);     // 864 floats
    float*  x1s   = maskv;                          // 512 floats (overlay)
    float*  res   = maskv;                          // 512 floats (overlay)
    __half* x1h   = (__half*)(smem_raw + 43776);    // 512 halves

    int tid = threadIdx.x;
    int vb = blockIdx.x * VX;
    int x0 = vb % WW; int t = vb / WW;
    int y = t % HH; t /= HH;
    int z = t % DD; int n = t / DD;

    int lane = tid & 31, warp = tid >> 5;

    // ---- phase 1a: stage dw weights + input slab (3 x 3 x 10 x 64) ----
    for (int e = tid; e < CC * 27 / 4; e += 256)            // 432 float4
        ((float4*)dwws)[e] = ((const float4*)dw_w)[e];
    bool interior = (z >= 1) && (z <= DD - 2) && (y >= 1) && (y <= HH - 2)
                 && (x0 >= 1) && (x0 + VX <= WW - 1);
    if (interior) {
        const float* ib = input + ((size_t)((n * DD + z - 1) * HH + y - 1) * WW
                                   + x0 - 1) * CC;
        for (int e = tid; e < 3 * 3 * 10 * 16; e += 256) {  // 1440 float4
            int c4 = e & 15;
            int xx = (e >> 4) % 10;
            int r = e / 160;
            int yy = r % 3, zz = r / 3;
            ((float4*)slab)[e] =
                ((const float4*)(ib + ((size_t)(zz * HH + yy) * WW + xx) * CC))[c4];
        }
    } else {
        for (int e = tid; e < 3 * 3 * 10 * 16; e += 256) {
            int c4 = e & 15;
            int xx = (e >> 4) % 10;
            int r = e / 160;
            int yy = r % 3, zz = r / 3;
            int gz = z + zz - 1, gy = y + yy - 1, gx = x0 + xx - 1;
            float4 val = make_float4(0.f, 0.f, 0.f, 0.f);
            if ((unsigned)gz < DD && (unsigned)gy < HH && (unsigned)gx < WW)
                val = ((const float4*)(input + ((size_t)((n * DD + gz) * HH + gy) * WW + gx) * CC))[c4];
            ((float4*)slab)[e] = val;
        }
    }
    __syncthreads();

    // ---- phase 1b: depthwise conv, sliding window in x ----
    {
        int c = tid & 63, pair = tid >> 6;     // pair in 0..3
        int v0 = pair * 2;
        float acc0 = dw_b[c], acc1 = acc0;
#pragma unroll
        for (int zz = 0; zz < 3; zz++) {
#pragma unroll
            for (int yy = 0; yy < 3; yy++) {
                const float* srow = slab + ((zz * 3 + yy) * 10 + v0) * CC + c;
                const float* wrow = dwws + c * 27 + zz * 9 + yy * 3;
                float s0 = srow[0];
                float s1 = srow[CC];
                float s2 = srow[2 * CC];
                float s3 = srow[3 * CC];
                float w0 = wrow[0], w1 = wrow[1], w2 = wrow[2];
                acc0 = fmaf(s0, w0, fmaf(s1, w1, fmaf(s2, w2, acc0)));
                acc1 = fmaf(s1, w0, fmaf(s2, w1, fmaf(s3, w2, acc1)));
            }
        }
        x1s[v0 * CC + c] = acc0;
        x1s[(v0 + 1) * CC + c] = acc1;
    }
    __syncthreads();

    // ---- phase 2: LayerNorm + exact GELU (warp = voxel), write fp16 x1h ----
    {
        int v = warp;
        float a = x1s[v * CC + lane];
        float b = x1s[v * CC + lane + 32];
        float s = a + b, s2 = a * a + b * b;
#pragma unroll
        for (int o = 16; o > 0; o >>= 1) {
            s  += __shfl_xor_sync(0xffffffffu, s,  o);
            s2 += __shfl_xor_sync(0xffffffffu, s2, o);
        }
        float mean = s * (1.0f / CC);
        float var  = s2 * (1.0f / CC) - mean * mean;
        float rstd = rsqrtf(var + 1e-6f);
        a = (a - mean) * rstd * ln_g[lane] + ln_b[lane];
        b = (b - mean) * rstd * ln_g[lane + 32] + ln_b[lane + 32];
        a = 0.5f * a * (1.0f + erff(a * 0.70710678118654752f));
        b = 0.5f * b * (1.0f + erff(b * 0.70710678118654752f));
        x1h[v * CC + lane]      = __float2half(a);
        x1h[v * CC + lane + 32] = __float2half(b);
    }
    __syncthreads();

    // ---- phase 3: heads GEMM on tensor cores (m16n8k16, fp16 in, fp32 acc).
    {
        int g = lane >> 2, tg = lane & 3;
        unsigned a0[4], a2[4];
        const __half* xr = x1h + g * CC;
#pragma unroll
        for (int ks = 0; ks < 4; ks++) {
            a0[ks] = *(const unsigned*)(xr + ks * 16 + tg * 2);
            a2[ks] = *(const unsigned*)(xr + ks * 16 + 8 + tg * 2);
        }
        for (int nt = warp; nt < 54; nt += 8) {
            float c0 = 0.f, c1 = 0.f, c2 = 0.f, c3 = 0.f;
#pragma unroll
            for (int ks = 0; ks < 4; ks++) {
                uint2 wq = g_wB[(nt * 4 + ks) * 32 + lane];
                asm volatile(
                    "mma.sync.aligned.m16n8k16.row.col.f32.f16.f16.f32 "
                    "{%0,%1,%2,%3},{%4,%5,%6,%7},{%8,%9},{%0,%1,%2,%3};"
                    : "+f"(c0), "+f"(c1), "+f"(c2), "+f"(c3)
                    : "r"(a0[ks]), "r"(0u), "r"(a2[ks]), "r"(0u),
                      "r"(wq.x), "r"(wq.y));
            }
            int n0 = nt * 8 + tg * 2;              // even; n0,n0+1 same head
            if (n0 < 324) {
                float2 bb = *(const float2*)(off_b + n0);
                float2 st = make_float2(c0 + bb.x, c1 + bb.y);
                *(float2*)(offs + g * 324 + n0) = st;
            } else {
                float2 bb = *(const float2*)(mask_b + (n0 - 324));
                float2 st = make_float2(c0 + bb.x, c1 + bb.y);
                *(float2*)(maskv + g * 108 + (n0 - 324)) = st;
            }
        }
    }
    __syncthreads();

    // ---- phase 4: softmax over P per (voxel, group), warp per 4 rows ----
    {
#pragma unroll
        for (int rr = 0; rr < 4; rr++) {
            int row = warp * 4 + rr;
            float val = (lane < PP) ? maskv[row * PP + lane] : -1e30f;
            float mx = val;
#pragma unroll
            for (int o = 16; o > 0; o >>= 1)
                mx = fmaxf(mx, __shfl_xor_sync(0xffffffffu, mx, o));
            float e = (lane < PP) ? __expf(val - mx) : 0.0f;
            float s = e;
#pragma unroll
            for (int o = 16; o > 0; o >>= 1)
                s += __shfl_xor_sync(0xffffffffu, s, o);
            if (lane < PP) maskv[row * PP + lane] = __fdividef(e, s);
        }
    }
    __syncthreads();

    // ---- phase 4.5: precompute packed sampling params, e = (g*27+p)*8+v ----
    for (int e = tid; e < VX * GG * PP; e += 256) {
        int v = e & 7, gp = e >> 3;
        int g = gp / 27, p = gp % 27;
        int i0 = p / 9, i1 = (p / 3) % 3, i2 = p % 3;       // (kw, kh, kd)
        const float* ofv = offs + v * 324 + (g * 27 + p) * 3;
        float px = (float)(x0 + v + i0) + ofv[0];
        float py = (float)(y + i1) + ofv[1];
        float pz = (float)(z + i2) + ofv[2];
        float fx0 = floorf(px), fy0 = floorf(py), fz0 = floorf(pz);
        int xi = (int)fx0, yi = (int)fy0, zi = (int)fz0;
        float fz = pz - fz0;
        float m  = maskv[v * 108 + g * 27 + p];
        pA[e] = make_float2(m * (1.0f - fz), m * fz);
        pB[e] = make_float2(px - fx0, py - fy0);
        int mbits = ((unsigned)xi       < WINP ?  1 : 0)
                  | ((unsigned)(xi + 1) < WINP ?  2 : 0)
                  | ((unsigned)yi       < HINP ?  4 : 0)
                  | ((unsigned)(yi + 1) < HINP ?  8 : 0)
                  | ((unsigned)zi       < DINP ? 16 : 0)
                  | ((unsigned)(zi + 1) < DINP ? 32 : 0);
        int base = ((zi * HINP + yi) * WINP + xi) * GCH;
        pC[e] = make_int2(base, mbits);
    }
    __syncthreads();

    // ---- phase 5: deformable trilinear sampling, cross-voxel coalesced.
    // Output written as fp16 (consumed by phase-6 tensor-core projection).
    {
        int dx = lane & 1, q2 = (lane >> 1) & 1, v = lane >> 2;
        int g = warp & 3, phalf = warp >> 2;
        int pstart = phalf ? 14 : 0;
        int pend   = phalf ? 27 : 14;
        __half* outp = phalf ? outhB : outhA;
        const __half* xgl = g_xph +
            (size_t)(n * GG + g) * (DINP * HINP * WINP) * GCH
            + dx * GCH + q2 * 8;                   // lane-fixed part of address
        float4 aA = make_float4(0.f, 0.f, 0.f, 0.f);
        float4 aB = make_float4(0.f, 0.f, 0.f, 0.f);
        for (int p = pstart; p < pend; p++) {
            int idx = (g * 27 + p) * 8 + v;
            float2 wzp = pA[idx];                  // mask pre-folded z weights
            float2 fxy = pB[idx];
            int2   bm  = pC[idx];
            int mb = bm.y;
            bool bxl = (mb >> dx) & 1;             // this lane's x corner
            float wxl = dx ? fxy.x : 1.0f - fxy.x;
            float wy0 = 1.0f - fxy.y, wy1 = fxy.y;
            const __half* bp = xgl + bm.x;
#pragma unroll
            for (int dz = 0; dz < 2; dz++) {
                bool bz = (mb & (16 << dz)) != 0;
                float wz = dz ? wzp.y : wzp.x;
#pragma unroll
                for (int dy = 0; dy < 2; dy++) {
                    bool ok = bxl && bz && ((mb & (4 << dy)) != 0);
                    if (ok) {
                        float wt = wz * (dy ? wy1 : wy0) * wxl;
                        uint4 raw = *(const uint4*)(bp +
                            (dz * (HINP * WINP) + dy * WINP) * GCH);
                        const __half2* hp = (const __half2*)&raw;
                        float2 f0 = __half22float2(hp[0]);
                        float2 f1 = __half22float2(hp[1]);
                        float2 f2 = __half22float2(hp[2]);
                        float2 f3 = __half22float2(hp[3]);
                        aA.x = fmaf(wt, f0.x, aA.x);
                        aA.y = fmaf(wt, f0.y, aA.y);
                        aA.z = fmaf(wt, f1.x, aA.z);
                        aA.w = fmaf(wt, f1.y, aA.w);
                        aB.x = fmaf(wt, f2.x, aB.x);
                        aB.y = fmaf(wt, f2.y, aB.y);
                        aB.z = fmaf(wt, f3.x, aB.z);
                        aB.w = fmaf(wt, f3.y, aB.w);
                    }
                }
            }
        }
        // reduce over dx (xor 1)
        aA.x += __shfl_xor_sync(0xffffffffu, aA.x, 1);
        aA.y += __shfl_xor_sync(0xffffffffu, aA.y, 1);
        aA.z += __shfl_xor_sync(0xffffffffu, aA.z, 1);
        aA.w += __shfl_xor_sync(0xffffffffu, aA.w, 1);
        aB.x += __shfl_xor_sync(0xffffffffu, aB.x, 1);
        aB.y += __shfl_xor_sync(0xffffffffu, aB.y, 1);
        aB.z += __shfl_xor_sync(0xffffffffu, aB.z, 1);
        aB.w += __shfl_xor_sync(0xffffffffu, aB.w, 1);
        if (dx == 0) {
            uint4 u;
            ((__half2*)&u)[0] = __floats2half2_rn(aA.x, aA.y);
            ((__half2*)&u)[1] = __floats2half2_rn(aA.z, aA.w);
            ((__half2*)&u)[2] = __floats2half2_rn(aB.x, aB.y);
            ((__half2*)&u)[3] = __floats2half2_rn(aB.z, aB.w);
            *(uint4*)(outp + v * CC + g * GCH + q2 * 8) = u;
        }
    }
    __syncthreads();

    // ---- phase 6: output projection on tensor cores (m16n8k16).
    // A rows 0..7 = voxels (outhA + outhB, fp16); 8 n-tiles, warp = tile.
    {
        int g = lane >> 2, tg = lane & 3;
        unsigned a0[4], a2[4];
        const __half* xa = outhA + g * CC;
        const __half* xb = outhB + g * CC;
#pragma unroll
        for (int ks = 0; ks < 4; ks++) {
            __half2 lo = __hadd2(*(const __half2*)(xa + ks * 16 + tg * 2),
                                 *(const __half2*)(xb + ks * 16 + tg * 2));
            __half2 hi = __hadd2(*(const __half2*)(xa + ks * 16 + 8 + tg * 2),
                                 *(const __half2*)(xb + ks * 16 + 8 + tg * 2));
            a0[ks] = *(unsigned*)&lo;
            a2[ks] = *(unsigned*)&hi;
        }
        int nt = warp;                             // 8 warps, 8 n-tiles
        float c0 = 0.f, c1 = 0.f, c2 = 0.f, c3 = 0.f;
#pragma unroll
        for (int ks = 0; ks < 4; ks++) {
            uint2 wq = g_wO[(nt * 4 + ks) * 32 + lane];
            asm volatile(
                "mma.sync.aligned.m16n8k16.row.col.f32.f16.f16.f32 "
                "{%0,%1,%2,%3},{%4,%5,%6,%7},{%8,%9},{%0,%1,%2,%3};"
                : "+f"(c0), "+f"(c1), "+f"(c2), "+f"(c3)
                : "r"(a0[ks]), "r"(0u), "r"(a2[ks]), "r"(0u),
                  "r"(wq.x), "r"(wq.y));
        }
        __syncthreads();   // maskv (overlaid by res) fully dead; safe reuse
        int n0 = nt * 8 + tg * 2;
        float2 bb = *(const float2*)(out_b + n0);
        *(float2*)(res + g * CC + n0) = make_float2(c0 + bb.x, c1 + bb.y);
    }
    __syncthreads();

    if (tid < 128)
        ((float4*)(out + (size_t)vb * CC))[tid] = ((const float4*)res)[tid];
}

extern "C" void kernel_launch(void* const* d_in, const int* in_sizes, int n_in,
                              void* d_out, int out_size)
{
    const float* input  = (const float*)d_in[0];
    const float* dw_w   = (const float*)d_in[1];
    const float* dw_b   = (const float*)d_in[2];
    const float* ln_g   = (const float*)d_in[3];
    const float* ln_b   = (const float*)d_in[4];
    const float* off_w  = (const float*)d_in[5];
    const float* off_b  = (const float*)d_in[6];
    const float* mask_w = (const float*)d_in[7];
    const float* mask_b = (const float*)d_in[8];
    const float* in_w   = (const float*)d_in[9];
    const float* in_b   = (const float*)d_in[10];
    const float* out_w  = (const float*)d_in[11];
    const float* out_b  = (const float*)d_in[12];
    float* out = (float*)d_out;

    int blocks = NB * DD * HH * WW / VX;               // 4096

    proj_pad_kernel<<<blocks, 256>>>(input, in_w, in_b, off_w, mask_w, out_w);
    dcnv3_fused_kernel<<<blocks, 256>>>(
        input, dw_w, dw_b, ln_g, ln_b,
        off_b, mask_b, out_b, out);
}